// round 10
// baseline (speedup 1.0000x reference)
#include <cuda_runtime.h>
#include <cstdint>

// Problem dims (fixed by the dataset)
#define B_  64
#define T_  256
#define D_  512
#define H_  1024
#define M_  (B_ * T_)   // 16384

// GEMM tiling
#define BM 128
#define BN 128
#define BK 16

// Scratch (allocation-free rule: __device__ globals)
__device__ float g_pre[(size_t)M_ * H_];   // 64 MB: pre-activations
__device__ float g_part[256];

// ---------------------------------------------------------------------------
// Kernel 1: g_pre[m,n] = sum_k A[m,k] * W[n,k] + bias[n]
// 128x128x16 double-buffered SGEMM, 256 threads, 8x8 per-thread tile.
// B stored DUPLICATED in smem ({b,b} pairs) so FFMA2 broadcast operands come
// straight from LDS.128; accumulators paired over adjacent m (A float4s are
// m-contiguous). Inner k-step: 32 FFMA2 + 6 LDS.128, zero packing MOVs.
// Per-component k-ascending FFMA chain == scalar version (bitwise identical).
// ---------------------------------------------------------------------------
__global__ __launch_bounds__(256, 2) void gemm_bias_kernel(
    const float* __restrict__ A,
    const float* __restrict__ W,
    const float* __restrict__ bias)
{
    __shared__ float sA[2][BK][BM];        // 16 KB
    __shared__ float sB[2][BK][2 * BN];    // 32 KB (duplicated pairs)

    const int tid = threadIdx.x;
    const int bm = blockIdx.y * BM;
    const int bn = blockIdx.x * BN;

    // Loader mapping: thread -> (row lrow, k-offset lcol), 8 k per thread
    const int lrow = tid >> 1;             // 0..127
    const int lcol = (tid & 1) * 8;        // 0 or 8
    const float* Ap = A + (size_t)(bm + lrow) * D_ + lcol;
    const float* Wp = W + (size_t)(bn + lrow) * D_ + lcol;

    // Prime buffer 0
    {
        float4 a0 = *(const float4*)Ap;
        float4 a1 = *(const float4*)(Ap + 4);
        float4 w0 = *(const float4*)Wp;
        float4 w1 = *(const float4*)(Wp + 4);
        sA[0][lcol + 0][lrow] = a0.x; sA[0][lcol + 1][lrow] = a0.y;
        sA[0][lcol + 2][lrow] = a0.z; sA[0][lcol + 3][lrow] = a0.w;
        sA[0][lcol + 4][lrow] = a1.x; sA[0][lcol + 5][lrow] = a1.y;
        sA[0][lcol + 6][lrow] = a1.z; sA[0][lcol + 7][lrow] = a1.w;
        const float wv[8] = {w0.x, w0.y, w0.z, w0.w, w1.x, w1.y, w1.z, w1.w};
#pragma unroll
        for (int q = 0; q < 8; q++)
            *(float2*)&sB[0][lcol + q][2 * lrow] = make_float2(wv[q], wv[q]);
    }
    __syncthreads();

    const int tx = tid & 15;   // n-direction
    const int ty = tid >> 4;   // m-direction

    // acc2[ip][j]: ip = m-pair (0..3), j = n (0..7); lo 32 bits = even m.
    unsigned long long acc2[4][8];
#pragma unroll
    for (int ip = 0; ip < 4; ip++)
#pragma unroll
        for (int j = 0; j < 8; j++) acc2[ip][j] = 0ull;

    int buf = 0;
    for (int k0 = BK; k0 <= D_; k0 += BK) {
        const bool more = (k0 < D_);
        float4 na0, na1, nw0, nw1;
        if (more) {
            na0 = *(const float4*)(Ap + k0);
            na1 = *(const float4*)(Ap + k0 + 4);
            nw0 = *(const float4*)(Wp + k0);
            nw1 = *(const float4*)(Wp + k0 + 4);
        }
#pragma unroll
        for (int kk = 0; kk < BK; kk++) {
            // A: 2 LDS.128 -> 4 packed m-pairs
            unsigned long long a2[4];
            *(ulonglong2*)&a2[0] = *(const ulonglong2*)&sA[buf][kk][ty * 4];
            *(ulonglong2*)&a2[2] = *(const ulonglong2*)&sA[buf][kk][64 + ty * 4];
            // B: 4 LDS.128 -> 8 packed {b,b} broadcast pairs
            unsigned long long b2[8];
            *(ulonglong2*)&b2[0] = *(const ulonglong2*)&sB[buf][kk][2 * (tx * 4)];
            *(ulonglong2*)&b2[2] = *(const ulonglong2*)&sB[buf][kk][2 * (tx * 4) + 4];
            *(ulonglong2*)&b2[4] = *(const ulonglong2*)&sB[buf][kk][2 * (64 + tx * 4)];
            *(ulonglong2*)&b2[6] = *(const ulonglong2*)&sB[buf][kk][2 * (64 + tx * 4) + 4];
#pragma unroll
            for (int ip = 0; ip < 4; ip++)
#pragma unroll
                for (int j = 0; j < 8; j++)
                    asm("fma.rn.f32x2 %0, %1, %2, %0;"
                        : "+l"(acc2[ip][j])
                        : "l"(a2[ip]), "l"(b2[j]));
        }
        if (more) {
            buf ^= 1;
            sA[buf][lcol + 0][lrow] = na0.x; sA[buf][lcol + 1][lrow] = na0.y;
            sA[buf][lcol + 2][lrow] = na0.z; sA[buf][lcol + 3][lrow] = na0.w;
            sA[buf][lcol + 4][lrow] = na1.x; sA[buf][lcol + 5][lrow] = na1.y;
            sA[buf][lcol + 6][lrow] = na1.z; sA[buf][lcol + 7][lrow] = na1.w;
            const float wv[8] = {nw0.x, nw0.y, nw0.z, nw0.w, nw1.x, nw1.y, nw1.z, nw1.w};
#pragma unroll
            for (int q = 0; q < 8; q++)
                *(float2*)&sB[buf][lcol + q][2 * lrow] = make_float2(wv[q], wv[q]);
            __syncthreads();
        }
    }

    // Unpack m-paired accumulators to scalar 8x8 view: acc[i][j], i = m-frag row
    float acc[8][8];
#pragma unroll
    for (int ip = 0; ip < 4; ip++)
#pragma unroll
        for (int j = 0; j < 8; j++) {
            acc[2 * ip + 0][j] = __uint_as_float((uint32_t)(acc2[ip][j]));
            acc[2 * ip + 1][j] = __uint_as_float((uint32_t)(acc2[ip][j] >> 32));
        }

    // Epilogue: add bias, store
    float bs[8];
#pragma unroll
    for (int j = 0; j < 8; j++) {
        int n = bn + ((j < 4) ? (tx * 4 + j) : (64 + tx * 4 + (j - 4)));
        bs[j] = bias[n];
    }
#pragma unroll
    for (int i = 0; i < 8; i++) {
        int m = bm + ((i < 4) ? (ty * 4 + i) : (64 + ty * 4 + (i - 4)));
        float4 v0 = make_float4(acc[i][0] + bs[0], acc[i][1] + bs[1],
                                acc[i][2] + bs[2], acc[i][3] + bs[3]);
        float4 v1 = make_float4(acc[i][4] + bs[4], acc[i][5] + bs[5],
                                acc[i][6] + bs[6], acc[i][7] + bs[7]);
        *(float4*)&g_pre[(size_t)m * H_ + bn + tx * 4] = v0;
        *(float4*)&g_pre[(size_t)m * H_ + bn + 64 + tx * 4] = v1;
    }
}

// ---------------------------------------------------------------------------
// Kernel 2: ALIF recurrence over T per (b,h), then weighted partial reduce.
// ---------------------------------------------------------------------------
__global__ __launch_bounds__(256) void alif_scan_kernel(
    const float* __restrict__ W_out)
{
    const int b  = blockIdx.x >> 2;
    const int hc = blockIdx.x & 3;
    const int h  = hc * 256 + threadIdx.x;

    const float* p = g_pre + (size_t)b * T_ * H_ + h;

    float mem = 0.0f, adapt = 0.0f, cnt = 0.0f;
#pragma unroll 8
    for (int t = 0; t < T_; t++) {
        float v = p[(size_t)t * H_];
        mem = 0.9f * mem + v - adapt;
        float spk = (mem > 0.0f) ? 1.0f : 0.0f;
        adapt += 0.1f * spk;
        mem -= spk;
        cnt += spk;
    }

    float val = cnt * (1.0f / (float)T_) * W_out[h];

    __shared__ float red[256];
    red[threadIdx.x] = val;
    __syncthreads();
#pragma unroll
    for (int s = 128; s > 0; s >>= 1) {
        if (threadIdx.x < s) red[threadIdx.x] += red[threadIdx.x + s];
        __syncthreads();
    }
    if (threadIdx.x == 0) g_part[blockIdx.x] = red[0];
}

// ---------------------------------------------------------------------------
// Kernel 3: out[b] = sum_c g_part[b*4+c] + b_out[0]
// ---------------------------------------------------------------------------
__global__ void finalize_kernel(const float* __restrict__ b_out,
                                float* __restrict__ out)
{
    int b = threadIdx.x;
    if (b < B_) {
        float s = g_part[b * 4 + 0] + g_part[b * 4 + 1] +
                  g_part[b * 4 + 2] + g_part[b * 4 + 3];
        out[b] = s + b_out[0];
    }
}

extern "C" void kernel_launch(void* const* d_in, const int* in_sizes, int n_in,
                              void* d_out, int out_size)
{
    (void)in_sizes; (void)n_in; (void)out_size;
    const float* x     = (const float*)d_in[0];  // [64,256,512]
    const float* W_in  = (const float*)d_in[1];  // [1024,512]
    const float* b_in  = (const float*)d_in[2];  // [1024]
    const float* W_out = (const float*)d_in[3];  // [1,1024]
    const float* b_out = (const float*)d_in[4];  // [1]
    float* out = (float*)d_out;                  // [64,1]

    dim3 ggrid(H_ / BN, M_ / BM);                // (8, 128)
    gemm_bias_kernel<<<ggrid, 256>>>(x, W_in, b_in);
    alif_scan_kernel<<<256, 256>>>(W_out);
    finalize_kernel<<<1, 64>>>(b_out, out);
}

// round 11
// speedup vs baseline: 1.1268x; 1.1268x over previous
#include <cuda_runtime.h>
#include <cstdint>

// Problem dims (fixed by the dataset)
#define B_  64
#define T_  256
#define D_  512
#define H_  1024
#define M_  (B_ * T_)   // 16384

// GEMM tiling
#define BM 128
#define BN 128
#define BK 16
#define NTILES (D_ / BK)   // 32

// Scratch (allocation-free rule: __device__ globals)
__device__ float g_pre[(size_t)M_ * H_];   // 64 MB: pre-activations
__device__ float g_part[256];

__device__ __forceinline__ uint32_t smem_u32(const void* p) {
    uint32_t a;
    asm("{ .reg .u64 t; cvta.to.shared.u64 t, %1; cvt.u32.u64 %0, t; }"
        : "=r"(a) : "l"(p));
    return a;
}

// 4-byte cp.async (scatter-capable: lets us write the transposed smem layout)
__device__ __forceinline__ void cp4(uint32_t dst, const float* src) {
    asm volatile(
        "{ .reg .u64 g; cvta.to.global.u64 g, %1; "
        "cp.async.ca.shared.global [%0], [g], 4; }"
        :: "r"(dst), "l"(src) : "memory");
}
#define CP_COMMIT() asm volatile("cp.async.commit_group;" ::: "memory")
#define CP_WAIT0()  asm volatile("cp.async.wait_group 0;" ::: "memory")

// ---------------------------------------------------------------------------
// Kernel 1: g_pre[m,n] = sum_k A[m,k] * W[n,k] + bias[n]
// 128x128x16 SGEMM, 256 threads, 8x8 per-thread tile (4+4 split fragments).
// Global->smem via cp.async (2-stage), freeing prefetch registers so ptxas
// can schedule LDS fragments ahead of the FFMA2 chain. Inner loop identical
// to the best R8 config: n-paired fma.rn.f32x2, per-accumulator ascending-k
// chain => bitwise identical to scalar FFMA.
// ---------------------------------------------------------------------------
__global__ __launch_bounds__(256, 2) void gemm_bias_kernel(
    const float* __restrict__ A,
    const float* __restrict__ W,
    const float* __restrict__ bias)
{
    __shared__ float sA[2][BK][BM];    // 16 KB
    __shared__ float sB[2][BK][BN];    // 16 KB

    const int tid = threadIdx.x;
    const int bm = blockIdx.y * BM;
    const int bn = blockIdx.x * BN;

    // Loader mapping: thread -> (row lrow, k-offset lcol), 8 k per thread
    const int lrow = tid >> 1;             // 0..127
    const int lcol = (tid & 1) * 8;        // 0 or 8
    const float* Ap = A + (size_t)(bm + lrow) * D_ + lcol;
    const float* Wp = W + (size_t)(bn + lrow) * D_ + lcol;

    // Per-stage smem destinations for this thread's 8+8 scattered 4B copies
    uint32_t dA[2], dB[2];
    dA[0] = smem_u32(&sA[0][lcol][lrow]);
    dA[1] = smem_u32(&sA[1][lcol][lrow]);
    dB[0] = smem_u32(&sB[0][lcol][lrow]);
    dB[1] = smem_u32(&sB[1][lcol][lrow]);
    const uint32_t rowStride = BM * 4;     // bytes between consecutive k rows

    auto issue_tile = [&](int it, int st) {
        const int k0 = it * BK;
#pragma unroll
        for (int q = 0; q < 8; q++) {
            cp4(dA[st] + (uint32_t)q * rowStride, Ap + k0 + q);
            cp4(dB[st] + (uint32_t)q * rowStride, Wp + k0 + q);
        }
        CP_COMMIT();
    };

    const int tx = tid & 15;   // n-direction
    const int ty = tid >> 4;   // m-direction

    // acc2[i][jp]: i = m-row (0..7), jp = n-pair (0..3); lo 32 bits = even n.
    unsigned long long acc2[8][4];
#pragma unroll
    for (int i = 0; i < 8; i++)
#pragma unroll
        for (int jp = 0; jp < 4; jp++) acc2[i][jp] = 0ull;

    issue_tile(0, 0);

    for (int it = 0; it < NTILES; ++it) {
        const int buf = it & 1;
        CP_WAIT0();
        __syncthreads();
        if (it + 1 < NTILES) issue_tile(it + 1, buf ^ 1);

#pragma unroll
        for (int kk = 0; kk < BK; kk++) {
            float ra[8];
            unsigned long long rb2[4];
            *(float4*)&ra[0] = *(const float4*)&sA[buf][kk][ty * 4];
            *(float4*)&ra[4] = *(const float4*)&sA[buf][kk][64 + ty * 4];
            *(ulonglong2*)&rb2[0] = *(const ulonglong2*)&sB[buf][kk][tx * 4];
            *(ulonglong2*)&rb2[2] = *(const ulonglong2*)&sB[buf][kk][64 + tx * 4];
#pragma unroll
            for (int i = 0; i < 8; i++) {
                unsigned long long a2;
                asm("mov.b64 %0, {%1, %1};" : "=l"(a2) : "f"(ra[i]));
#pragma unroll
                for (int jp = 0; jp < 4; jp++) {
                    asm("fma.rn.f32x2 %0, %1, %2, %0;"
                        : "+l"(acc2[i][jp])
                        : "l"(a2), "l"(rb2[jp]));
                }
            }
        }
        __syncthreads();
    }

    // Unpack accumulator pairs back to the scalar 8x8 view
    float acc[8][8];
#pragma unroll
    for (int i = 0; i < 8; i++)
#pragma unroll
        for (int jp = 0; jp < 4; jp++) {
            acc[i][2 * jp + 0] = __uint_as_float((uint32_t)(acc2[i][jp]));
            acc[i][2 * jp + 1] = __uint_as_float((uint32_t)(acc2[i][jp] >> 32));
        }

    // Epilogue: add bias, store
    float bs[8];
#pragma unroll
    for (int j = 0; j < 8; j++) {
        int n = bn + ((j < 4) ? (tx * 4 + j) : (64 + tx * 4 + (j - 4)));
        bs[j] = bias[n];
    }
#pragma unroll
    for (int i = 0; i < 8; i++) {
        int m = bm + ((i < 4) ? (ty * 4 + i) : (64 + ty * 4 + (i - 4)));
        float4 v0 = make_float4(acc[i][0] + bs[0], acc[i][1] + bs[1],
                                acc[i][2] + bs[2], acc[i][3] + bs[3]);
        float4 v1 = make_float4(acc[i][4] + bs[4], acc[i][5] + bs[5],
                                acc[i][6] + bs[6], acc[i][7] + bs[7]);
        *(float4*)&g_pre[(size_t)m * H_ + bn + tx * 4] = v0;
        *(float4*)&g_pre[(size_t)m * H_ + bn + 64 + tx * 4] = v1;
    }
}

// ---------------------------------------------------------------------------
// Kernel 2: ALIF recurrence over T per (b,h), then weighted partial reduce.
// ---------------------------------------------------------------------------
__global__ __launch_bounds__(256) void alif_scan_kernel(
    const float* __restrict__ W_out)
{
    const int b  = blockIdx.x >> 2;
    const int hc = blockIdx.x & 3;
    const int h  = hc * 256 + threadIdx.x;

    const float* p = g_pre + (size_t)b * T_ * H_ + h;

    float mem = 0.0f, adapt = 0.0f, cnt = 0.0f;
#pragma unroll 8
    for (int t = 0; t < T_; t++) {
        float v = p[(size_t)t * H_];
        mem = 0.9f * mem + v - adapt;
        float spk = (mem > 0.0f) ? 1.0f : 0.0f;
        adapt += 0.1f * spk;
        mem -= spk;
        cnt += spk;
    }

    float val = cnt * (1.0f / (float)T_) * W_out[h];

    __shared__ float red[256];
    red[threadIdx.x] = val;
    __syncthreads();
#pragma unroll
    for (int s = 128; s > 0; s >>= 1) {
        if (threadIdx.x < s) red[threadIdx.x] += red[threadIdx.x + s];
        __syncthreads();
    }
    if (threadIdx.x == 0) g_part[blockIdx.x] = red[0];
}

// ---------------------------------------------------------------------------
// Kernel 3: out[b] = sum_c g_part[b*4+c] + b_out[0]
// ---------------------------------------------------------------------------
__global__ void finalize_kernel(const float* __restrict__ b_out,
                                float* __restrict__ out)
{
    int b = threadIdx.x;
    if (b < B_) {
        float s = g_part[b * 4 + 0] + g_part[b * 4 + 1] +
                  g_part[b * 4 + 2] + g_part[b * 4 + 3];
        out[b] = s + b_out[0];
    }
}

extern "C" void kernel_launch(void* const* d_in, const int* in_sizes, int n_in,
                              void* d_out, int out_size)
{
    (void)in_sizes; (void)n_in; (void)out_size;
    const float* x     = (const float*)d_in[0];  // [64,256,512]
    const float* W_in  = (const float*)d_in[1];  // [1024,512]
    const float* b_in  = (const float*)d_in[2];  // [1024]
    const float* W_out = (const float*)d_in[3];  // [1,1024]
    const float* b_out = (const float*)d_in[4];  // [1]
    float* out = (float*)d_out;                  // [64,1]

    dim3 ggrid(H_ / BN, M_ / BM);                // (8, 128)
    gemm_bias_kernel<<<ggrid, 256>>>(x, W_in, b_in);
    alif_scan_kernel<<<256, 256>>>(W_out);
    finalize_kernel<<<1, 64>>>(b_out, out);
}

// round 12
// speedup vs baseline: 1.9318x; 1.7143x over previous
#include <cuda_runtime.h>
#include <cstdint>

// Problem dims (fixed by the dataset)
#define B_  64
#define T_  256
#define D_  512
#define H_  1024
#define M_  (B_ * T_)   // 16384

// GEMM tiling
#define BM 128
#define BN 128
#define BK 8

// Scratch (allocation-free rule: __device__ globals)
__device__ float g_pre[(size_t)M_ * H_];   // 64 MB: pre-activations
__device__ float g_part[256];

// ---------------------------------------------------------------------------
// Kernel 1: g_pre[m,n] = sum_k A[m,k] * W[n,k] + bias[n]
// 128x128x8 double-buffered SGEMM, 256 threads, 8x8 per-thread tile with 4+4
// split fragments. Inner product uses packed fma.rn.f32x2 (FFMA2):
// accumulators paired over adjacent n, per-component RN => bitwise identical
// to the scalar-FFMA version. (R8 configuration, frozen: fma=69%, L1=78%.)
// ---------------------------------------------------------------------------
__global__ __launch_bounds__(256, 2) void gemm_bias_kernel(
    const float* __restrict__ A,
    const float* __restrict__ W,
    const float* __restrict__ bias)
{
    __shared__ float sA[2][BK][BM];
    __shared__ float sB[2][BK][BN];

    const int tid = threadIdx.x;
    const int bm = blockIdx.y * BM;
    const int bn = blockIdx.x * BN;

    // Global->smem load mapping: one float4 of A and one of W per thread per K-tile
    const int lrow = tid >> 1;        // 0..127
    const int lcol = (tid & 1) * 4;   // 0 or 4
    const float* Ap = A + (size_t)(bm + lrow) * D_ + lcol;
    const float* Wp = W + (size_t)(bn + lrow) * D_ + lcol;

    // Prime buffer 0
    {
        float4 a4 = *(const float4*)Ap;
        float4 w4 = *(const float4*)Wp;
        sA[0][lcol + 0][lrow] = a4.x; sA[0][lcol + 1][lrow] = a4.y;
        sA[0][lcol + 2][lrow] = a4.z; sA[0][lcol + 3][lrow] = a4.w;
        sB[0][lcol + 0][lrow] = w4.x; sB[0][lcol + 1][lrow] = w4.y;
        sB[0][lcol + 2][lrow] = w4.z; sB[0][lcol + 3][lrow] = w4.w;
    }
    __syncthreads();

    const int tx = tid & 15;   // n-direction, 16 threads
    const int ty = tid >> 4;   // m-direction, 16 threads

    // acc2[i][jp]: i = m-fragment row (0..7), jp = n-pair (0..3);
    // lo 32 bits = n=2*jp, hi = n=2*jp+1. 0ull == (0.0f, 0.0f).
    unsigned long long acc2[8][4];
#pragma unroll
    for (int i = 0; i < 8; i++)
#pragma unroll
        for (int jp = 0; jp < 4; jp++) acc2[i][jp] = 0ull;

    int buf = 0;
    for (int k0 = BK; k0 <= D_; k0 += BK) {
        const bool more = (k0 < D_);
        float4 na, nw;
        if (more) {
            na = *(const float4*)(Ap + k0);
            nw = *(const float4*)(Wp + k0);
        }
#pragma unroll
        for (int kk = 0; kk < BK; kk++) {
            float ra[8];
            unsigned long long rb2[4];
            *(float4*)&ra[0] = *(const float4*)&sA[buf][kk][ty * 4];
            *(float4*)&ra[4] = *(const float4*)&sA[buf][kk][64 + ty * 4];
            // B pairs read directly as packed 64-bit lanes (lo = lower n)
            *(ulonglong2*)&rb2[0] = *(const ulonglong2*)&sB[buf][kk][tx * 4];
            *(ulonglong2*)&rb2[2] = *(const ulonglong2*)&sB[buf][kk][64 + tx * 4];
#pragma unroll
            for (int i = 0; i < 8; i++) {
                unsigned long long a2;
                asm("mov.b64 %0, {%1, %1};" : "=l"(a2) : "f"(ra[i]));
#pragma unroll
                for (int jp = 0; jp < 4; jp++) {
                    asm("fma.rn.f32x2 %0, %1, %2, %0;"
                        : "+l"(acc2[i][jp])
                        : "l"(a2), "l"(rb2[jp]));
                }
            }
        }
        if (more) {
            buf ^= 1;
            sA[buf][lcol + 0][lrow] = na.x; sA[buf][lcol + 1][lrow] = na.y;
            sA[buf][lcol + 2][lrow] = na.z; sA[buf][lcol + 3][lrow] = na.w;
            sB[buf][lcol + 0][lrow] = nw.x; sB[buf][lcol + 1][lrow] = nw.y;
            sB[buf][lcol + 2][lrow] = nw.z; sB[buf][lcol + 3][lrow] = nw.w;
            __syncthreads();
        }
    }

    // Unpack accumulator pairs back to the scalar 8x8 view
    float acc[8][8];
#pragma unroll
    for (int i = 0; i < 8; i++)
#pragma unroll
        for (int jp = 0; jp < 4; jp++) {
            acc[i][2 * jp + 0] = __uint_as_float((uint32_t)(acc2[i][jp]));
            acc[i][2 * jp + 1] = __uint_as_float((uint32_t)(acc2[i][jp] >> 32));
        }

    // Epilogue: add bias, store
    float bs[8];
#pragma unroll
    for (int j = 0; j < 8; j++) {
        int n = bn + ((j < 4) ? (tx * 4 + j) : (64 + tx * 4 + (j - 4)));
        bs[j] = bias[n];
    }
#pragma unroll
    for (int i = 0; i < 8; i++) {
        int m = bm + ((i < 4) ? (ty * 4 + i) : (64 + ty * 4 + (i - 4)));
        float4 v0 = make_float4(acc[i][0] + bs[0], acc[i][1] + bs[1],
                                acc[i][2] + bs[2], acc[i][3] + bs[3]);
        float4 v1 = make_float4(acc[i][4] + bs[4], acc[i][5] + bs[5],
                                acc[i][6] + bs[6], acc[i][7] + bs[7]);
        *(float4*)&g_pre[(size_t)m * H_ + bn + tx * 4] = v0;
        *(float4*)&g_pre[(size_t)m * H_ + bn + 64 + tx * 4] = v1;
    }
}

// ---------------------------------------------------------------------------
// Kernel 2: ALIF recurrence over T per (b,h), then weighted partial reduce.
// 16-deep explicit load batches: 16 independent loads in flight per thread
// (2x the MLP of the unroll-8 version) before each 16-step recurrence run.
// Recurrence math and ordering unchanged.
// ---------------------------------------------------------------------------
__global__ __launch_bounds__(256) void alif_scan_kernel(
    const float* __restrict__ W_out)
{
    const int b  = blockIdx.x >> 2;
    const int hc = blockIdx.x & 3;
    const int h  = hc * 256 + threadIdx.x;

    const float* p = g_pre + (size_t)b * T_ * H_ + h;

    float mem = 0.0f, adapt = 0.0f, cnt = 0.0f;

    for (int t0 = 0; t0 < T_; t0 += 16) {
        float v[16];
#pragma unroll
        for (int q = 0; q < 16; q++)
            v[q] = p[(size_t)(t0 + q) * H_];
#pragma unroll
        for (int q = 0; q < 16; q++) {
            mem = 0.9f * mem + v[q] - adapt;
            float spk = (mem > 0.0f) ? 1.0f : 0.0f;
            adapt += 0.1f * spk;
            mem -= spk;
            cnt += spk;
        }
    }

    float val = cnt * (1.0f / (float)T_) * W_out[h];

    __shared__ float red[256];
    red[threadIdx.x] = val;
    __syncthreads();
#pragma unroll
    for (int s = 128; s > 0; s >>= 1) {
        if (threadIdx.x < s) red[threadIdx.x] += red[threadIdx.x + s];
        __syncthreads();
    }
    if (threadIdx.x == 0) g_part[blockIdx.x] = red[0];
}

// ---------------------------------------------------------------------------
// Kernel 3: out[b] = sum_c g_part[b*4+c] + b_out[0]
// ---------------------------------------------------------------------------
__global__ void finalize_kernel(const float* __restrict__ b_out,
                                float* __restrict__ out)
{
    int b = threadIdx.x;
    if (b < B_) {
        float s = g_part[b * 4 + 0] + g_part[b * 4 + 1] +
                  g_part[b * 4 + 2] + g_part[b * 4 + 3];
        out[b] = s + b_out[0];
    }
}

extern "C" void kernel_launch(void* const* d_in, const int* in_sizes, int n_in,
                              void* d_out, int out_size)
{
    (void)in_sizes; (void)n_in; (void)out_size;
    const float* x     = (const float*)d_in[0];  // [64,256,512]
    const float* W_in  = (const float*)d_in[1];  // [1024,512]
    const float* b_in  = (const float*)d_in[2];  // [1024]
    const float* W_out = (const float*)d_in[3];  // [1,1024]
    const float* b_out = (const float*)d_in[4];  // [1]
    float* out = (float*)d_out;                  // [64,1]

    dim3 ggrid(H_ / BN, M_ / BM);                // (8, 128)
    gemm_bias_kernel<<<ggrid, 256>>>(x, W_in, b_in);
    alif_scan_kernel<<<256, 256>>>(W_out);
    finalize_kernel<<<1, 64>>>(b_out, out);
}